// round 1
// baseline (speedup 1.0000x reference)
#include <cuda_runtime.h>
#include <cstdint>

#define NROWS 12000     // B*T = 8*1500
#define BDIMB 8
#define TDIM  1500
#define CDIM  512
#define VCNT  4096
#define KSEL  100

// ---------------- scratch (device globals: no allocations allowed) ----------------
__device__ __align__(16) float g_E[NROWS * CDIM];        // 24.6 MB  (tokens x C, row-major)
__device__ float g_esq[NROWS];
__device__ float g_csq[VCNT];
__device__ __align__(16) float g_D2[(size_t)NROWS * VCNT]; // 196.6 MB
__device__ int   g_codes[NROWS];
__device__ int   g_is64;
__device__ float g_row_loss[NROWS];
__device__ float g_row_match[NROWS];

// ---------------- helpers ----------------
__device__ __forceinline__ float warpSumF(float v) {
    #pragma unroll
    for (int o = 16; o > 0; o >>= 1) v += __shfl_down_sync(0xffffffffu, v, o);
    return v;
}
__device__ __forceinline__ int warpSumI(int v) {
    #pragma unroll
    for (int o = 16; o > 0; o >>= 1) v += __shfl_down_sync(0xffffffffu, v, o);
    return v;
}

// ---------------- int64-vs-int32 teacher_codes detection ----------------
// If the buffer is int64, words at odd indices (hi-words of codes 0..5999) are all 0.
// If int32, they are 6000 random codes in [0,4096) — essentially never all zero.
// Reads only the first 12000 int32 words: in-bounds under both interpretations.
__global__ void k_detect(const int* __restrict__ w) {
    __shared__ int any_nonzero;
    if (threadIdx.x == 0) any_nonzero = 0;
    __syncthreads();
    int bad = 0;
    for (int i = threadIdx.x; i < 6000; i += 256)
        if (w[2 * i + 1] != 0) bad = 1;
    if (bad) any_nonzero = 1;   // benign race
    __syncthreads();
    if (threadIdx.x == 0) g_is64 = (any_nonzero == 0) ? 1 : 0;
}

__global__ void k_normcodes(const int* __restrict__ w) {
    int i = blockIdx.x * 256 + threadIdx.x;
    if (i >= NROWS) return;
    // little-endian: lo word of an int64 < 4096 is the value
    g_codes[i] = g_is64 ? w[2 * i] : w[i];
}

// ---------------- transpose student_emb (B,C,T) -> g_E[(b*T+t)*C + c] ----------------
__global__ void k_transpose(const float* __restrict__ se) {
    __shared__ float tile[32][33];
    int b  = blockIdx.z;
    int t0 = blockIdx.x * 32;
    int c0 = blockIdx.y * 32;
    const float* src = se + (size_t)b * CDIM * TDIM;
    #pragma unroll
    for (int j = 0; j < 32; j += 8) {
        int c = c0 + threadIdx.y + j;
        int t = t0 + threadIdx.x;
        if (t < TDIM) tile[threadIdx.y + j][threadIdx.x] = src[(size_t)c * TDIM + t];
    }
    __syncthreads();
    #pragma unroll
    for (int j = 0; j < 32; j += 8) {
        int t = t0 + threadIdx.y + j;
        int c = c0 + threadIdx.x;
        if (t < TDIM) g_E[(size_t)(b * TDIM + t) * CDIM + c] = tile[threadIdx.x][threadIdx.y + j];
    }
}

// ---------------- row squared-norms (warp per row) ----------------
__global__ void k_esq() {
    int row  = blockIdx.x * 8 + (threadIdx.x >> 5);
    int lane = threadIdx.x & 31;
    if (row >= NROWS) return;
    const float4* p = (const float4*)(g_E + (size_t)row * CDIM);
    float s = 0.f;
    #pragma unroll
    for (int i = lane; i < CDIM / 4; i += 32) {
        float4 q = p[i];
        s += q.x * q.x + q.y * q.y + q.z * q.z + q.w * q.w;
    }
    s = warpSumF(s);
    if (lane == 0) g_esq[row] = s;
}

__global__ void k_csq(const float* __restrict__ cb) {
    int row  = blockIdx.x * 8 + (threadIdx.x >> 5);
    int lane = threadIdx.x & 31;
    if (row >= VCNT) return;
    const float4* p = (const float4*)(cb + (size_t)row * CDIM);
    float s = 0.f;
    #pragma unroll
    for (int i = lane; i < CDIM / 4; i += 32) {
        float4 q = p[i];
        s += q.x * q.x + q.y * q.y + q.z * q.z + q.w * q.w;
    }
    s = warpSumF(s);
    if (lane == 0) g_csq[row] = s;
}

// ---------------- GEMM: D2[n][v] = esq[n] + csq[v] - 2 * dot(E[n], CB[v]) ----------------
// 64x64 block tile, BK=16, 256 threads, 4x4 per thread, fp32.
__global__ void __launch_bounds__(256) k_gemm(const float* __restrict__ cb) {
    __shared__ __align__(16) float sA[16][68];  // row stride 272B = 17*16B -> float4-aligned
    __shared__ __align__(16) float sB[16][68];

    const int tid = threadIdx.x;
    const int bm = blockIdx.y * 64;
    const int bn = blockIdx.x * 64;
    const int lr = tid >> 2;          // 0..63 row within tile
    const int lk = (tid & 3) << 2;    // 0,4,8,12
    const int tx = tid & 15;          // N micro
    const int ty = tid >> 4;          // M micro

    const bool arow_ok = (bm + lr) < NROWS;
    const float* aptr = g_E + (size_t)(bm + lr) * CDIM + lk;
    const float* bptr = cb  + (size_t)(bn + lr) * CDIM + lk;

    float acc[4][4] = {};
    for (int k0 = 0; k0 < CDIM; k0 += 16) {
        float4 a4 = arow_ok ? *(const float4*)(aptr + k0) : make_float4(0.f, 0.f, 0.f, 0.f);
        float4 b4 = *(const float4*)(bptr + k0);
        __syncthreads();
        sA[lk + 0][lr] = a4.x; sA[lk + 1][lr] = a4.y; sA[lk + 2][lr] = a4.z; sA[lk + 3][lr] = a4.w;
        sB[lk + 0][lr] = b4.x; sB[lk + 1][lr] = b4.y; sB[lk + 2][lr] = b4.z; sB[lk + 3][lr] = b4.w;
        __syncthreads();
        #pragma unroll
        for (int kk = 0; kk < 16; kk++) {
            float4 av = *(const float4*)&sA[kk][ty << 2];
            float4 bv = *(const float4*)&sB[kk][tx << 2];
            float am[4] = {av.x, av.y, av.z, av.w};
            float bm_[4] = {bv.x, bv.y, bv.z, bv.w};
            #pragma unroll
            for (int i = 0; i < 4; i++)
                #pragma unroll
                for (int j = 0; j < 4; j++)
                    acc[i][j] = fmaf(am[i], bm_[j], acc[i][j]);
        }
    }

    #pragma unroll
    for (int i = 0; i < 4; i++) {
        int r = bm + (ty << 2) + i;
        if (r < NROWS) {
            float es = g_esq[r];
            int c0 = bn + (tx << 2);
            float4 o;
            o.x = es + g_csq[c0 + 0] - 2.f * acc[i][0];
            o.y = es + g_csq[c0 + 1] - 2.f * acc[i][1];
            o.z = es + g_csq[c0 + 2] - 2.f * acc[i][2];
            o.w = es + g_csq[c0 + 3] - 2.f * acc[i][3];
            *(float4*)(g_D2 + (size_t)r * VCNT + c0) = o;
        }
    }
}

// ---------------- per-row top-K select + loss ----------------
// One 256-thread block per row. 16 values per thread in registers.
// 4-pass radix select on float-as-uint keys (values clamped >= 0, monotone bits).
__global__ void __launch_bounds__(256) k_select(int dummy) {
    const int n   = blockIdx.x;
    const int tid = threadIdx.x;
    const float* row = g_D2 + (size_t)n * VCNT;

    float    v[16];
    unsigned key[16];
    unsigned long long lmin = ~0ull;
    #pragma unroll
    for (int i = 0; i < 16; i++) {
        int idx = tid + i * 256;
        float x = fmaxf(row[idx], 0.f);
        v[i] = x;
        key[i] = __float_as_uint(x);
        unsigned long long p = ((unsigned long long)key[i] << 32) | (unsigned)idx;
        lmin = (p < lmin) ? p : lmin;
    }

    __shared__ unsigned long long s_min;
    __shared__ unsigned hist[256];
    __shared__ unsigned s_prefix, s_krem;
    __shared__ float s_wf[8];
    __shared__ int   s_wc[8], s_we[8];

    if (tid == 0) { s_min = ~0ull; s_prefix = 0u; s_krem = KSEL; }
    __syncthreads();
    atomicMin(&s_min, lmin);

    // radix select: find the KSEL-th smallest key exactly
    for (int pass = 0; pass < 4; pass++) {
        int shift = 24 - 8 * pass;
        hist[tid] = 0;
        __syncthreads();
        unsigned pref = s_prefix;
        #pragma unroll
        for (int i = 0; i < 16; i++) {
            bool part = (pass == 0) || (((key[i] ^ pref) >> (shift + 8)) == 0u);
            if (part) atomicAdd(&hist[(key[i] >> shift) & 255u], 1u);
        }
        __syncthreads();
        if (tid == 0) {
            unsigned k = s_krem, cum = 0, b = 0;
            for (; b < 256u; b++) {
                unsigned c = hist[b];
                if (cum + c >= k) break;
                cum += c;
            }
            s_prefix |= b << shift;
            s_krem = k - cum;
        }
        __syncthreads();
    }

    const unsigned Tkey = s_prefix;
    const unsigned cb   = KSEL - s_krem;     // count strictly below threshold (<= 99)
    const unsigned long long mn = s_min;
    const float dmin = sqrtf(__uint_as_float((unsigned)(mn >> 32)));
    const int   amin = (int)(mn & 0xffffffffu);

    const int   code = g_codes[n];
    const float d2c  = fmaxf(__ldg(&row[code]), 0.f);
    const unsigned kc = __float_as_uint(d2c);

    // partials: sum of exp over keys < T; strict-less count vs code; equal-with-smaller-index count
    float sw = 0.f;
    int cl = 0, ce = 0;
    #pragma unroll
    for (int i = 0; i < 16; i++) {
        unsigned kk = key[i];
        if (kk < Tkey) sw += expf(dmin - sqrtf(v[i]));
        cl += (kk < kc);
        ce += (kk == kc) && ((tid + i * 256) < code);
    }
    sw = warpSumF(sw); cl = warpSumI(cl); ce = warpSumI(ce);
    int w = tid >> 5, lane = tid & 31;
    if (lane == 0) { s_wf[w] = sw; s_wc[w] = cl; s_we[w] = ce; }
    __syncthreads();

    if (tid == 0) {
        float swt = 0.f; int clt = 0, cet = 0;
        #pragma unroll
        for (int i = 0; i < 8; i++) { swt += s_wf[i]; clt += s_wc[i]; cet += s_we[i]; }

        float Td = sqrtf(__uint_as_float(Tkey));
        float wT = expf(dmin - Td);
        float dc = sqrtf(d2c);
        bool in_topk = (clt + cet) < KSEL;     // jax.lax.top_k tie-break: smaller index wins
        float S;
        if (in_topk) S = swt + (float)(KSEL - cb) * wT;             // code's term already inside
        else         S = swt + (float)(KSEL - 1 - cb) * wT + expf(dmin - dc);
        g_row_loss[n]  = dc - dmin + logf(S);
        g_row_match[n] = (amin == code) ? 1.f : 0.f;
    }
}

// ---------------- final deterministic reduction ----------------
__global__ void k_finalize(float* __restrict__ out) {
    __shared__ double sl[256], sm[256];
    int tid = threadIdx.x;
    double l = 0.0, m = 0.0;
    for (int i = tid; i < NROWS; i += 256) {
        l += (double)g_row_loss[i];
        m += (double)g_row_match[i];
    }
    sl[tid] = l; sm[tid] = m;
    __syncthreads();
    for (int s = 128; s > 0; s >>= 1) {
        if (tid < s) { sl[tid] += sl[tid + s]; sm[tid] += sm[tid + s]; }
        __syncthreads();
    }
    if (tid == 0) {
        out[0] = (float)(sl[0] / NROWS);   // loss
        out[1] = (float)(sm[0] / NROWS);   // local_accuracy  (== global modulo measure-zero ties)
        out[2] = (float)(sm[0] / NROWS);   // global_accuracy
        out[3] = 1.0f;                     // correct_in_candidates (forced replacement -> always 1)
    }
}

// ---------------- launch ----------------
extern "C" void kernel_launch(void* const* d_in, const int* in_sizes, int n_in,
                              void* d_out, int out_size) {
    const float* se    = (const float*)d_in[0];
    const int*   codes = (const int*)d_in[1];     // int32 or int64: detected at runtime
    const float* cb    = (const float*)d_in[2];
    float* out = (float*)d_out;
    (void)in_sizes; (void)n_in; (void)out_size;

    k_detect<<<1, 256>>>(codes);
    k_normcodes<<<(NROWS + 255) / 256, 256>>>(codes);
    k_transpose<<<dim3((TDIM + 31) / 32, CDIM / 32, BDIMB), dim3(32, 8)>>>(se);
    k_esq<<<(NROWS + 7) / 8, 256>>>();
    k_csq<<<VCNT / 8, 256>>>(cb);
    k_gemm<<<dim3(VCNT / 64, (NROWS + 63) / 64), 256>>>(cb);
    k_select<<<NROWS, 256>>>(0);
    k_finalize<<<1, 256>>>(out);
}

// round 3
// speedup vs baseline: 2.1721x; 2.1721x over previous
#include <cuda_runtime.h>
#include <cuda_bf16.h>
#include <cstdint>

#define NROWS 12000     // B*T = 8*1500
#define MPAD  12032     // 94 * 128
#define BDIMB 8
#define TDIM  1500
#define CDIM  512
#define VCNT  4096
#define KSEL  100

// ---- mma.sync GEMM tiling ----
#define BM 128
#define BN 128
#define BK 32
#define ROWB 80                       // smem leading dim: 40 bf16 = 80 B (16B-aligned, ldmatrix conflict-free)
#define OPBYTES (128 * ROWB)          // 10240 per operand matrix per stage
#define STG (4 * OPBYTES)             // 40960 (Ahi, Alo, Bhi, Blo)
#define NSTAGE 4
#define SMEM_GEMM (NSTAGE * STG)      // 163840
#define NKIT (CDIM / BK)              // 16

// ---------------- scratch (device globals: no allocations allowed) ----------------
__device__ __align__(16) float g_E[(size_t)NROWS * CDIM];
__device__ __align__(16) __nv_bfloat16 g_Ehi[(size_t)MPAD * CDIM]; // rows >= NROWS stay 0
__device__ __align__(16) __nv_bfloat16 g_Elo[(size_t)MPAD * CDIM];
__device__ __align__(16) __nv_bfloat16 g_Bhi[(size_t)VCNT * CDIM];
__device__ __align__(16) __nv_bfloat16 g_Blo[(size_t)VCNT * CDIM];
__device__ float g_esq[NROWS];
__device__ float g_csq[VCNT];
__device__ __align__(16) float g_D2[(size_t)NROWS * VCNT];         // 196.6 MB
__device__ int   g_codes[NROWS];
__device__ int   g_is64;
__device__ float g_row_loss[NROWS];
__device__ float g_row_match[NROWS];

// ---------------- helpers ----------------
__device__ __forceinline__ float warpSumF(float v) {
    #pragma unroll
    for (int o = 16; o > 0; o >>= 1) v += __shfl_down_sync(0xffffffffu, v, o);
    return v;
}
__device__ __forceinline__ int warpSumI(int v) {
    #pragma unroll
    for (int o = 16; o > 0; o >>= 1) v += __shfl_down_sync(0xffffffffu, v, o);
    return v;
}
__device__ __forceinline__ uint32_t smem_u32(const void* p) {
    uint32_t a;
    asm("{ .reg .u64 t; cvta.to.shared.u64 t, %1; cvt.u32.u64 %0, t; }" : "=r"(a) : "l"(p));
    return a;
}
__device__ __forceinline__ void cp16(uint32_t dst, const void* src) {
    asm volatile("cp.async.cg.shared.global [%0], [%1], 16;" :: "r"(dst), "l"(src));
}
#define LDSM4(r, a) \
    asm volatile("ldmatrix.sync.aligned.m8n8.x4.shared.b16 {%0,%1,%2,%3}, [%4];" \
        : "=r"((r)[0]), "=r"((r)[1]), "=r"((r)[2]), "=r"((r)[3]) : "r"(a))

__device__ __forceinline__ void mma16816(float* c, const uint32_t* a, const uint32_t* b) {
    asm volatile(
        "mma.sync.aligned.m16n8k16.row.col.f32.bf16.bf16.f32 "
        "{%0,%1,%2,%3}, {%4,%5,%6,%7}, {%8,%9}, {%0,%1,%2,%3};"
        : "+f"(c[0]), "+f"(c[1]), "+f"(c[2]), "+f"(c[3])
        : "r"(a[0]), "r"(a[1]), "r"(a[2]), "r"(a[3]), "r"(b[0]), "r"(b[1]));
}

// ---------------- int64-vs-int32 teacher_codes detection ----------------
__global__ void k_detect(const int* __restrict__ w) {
    __shared__ int any_nonzero;
    if (threadIdx.x == 0) any_nonzero = 0;
    __syncthreads();
    int bad = 0;
    for (int i = threadIdx.x; i < 6000; i += 256)
        if (w[2 * i + 1] != 0) bad = 1;
    if (bad) any_nonzero = 1;
    __syncthreads();
    if (threadIdx.x == 0) g_is64 = (any_nonzero == 0) ? 1 : 0;
}

__global__ void k_normcodes(const int* __restrict__ w) {
    int i = blockIdx.x * 256 + threadIdx.x;
    if (i >= NROWS) return;
    g_codes[i] = g_is64 ? w[2 * i] : w[i];
}

// ---------------- transpose student_emb (B,C,T) -> g_E[(b*T+t)*C + c] ----------------
__global__ void k_transpose(const float* __restrict__ se) {
    __shared__ float tile[32][33];
    int b  = blockIdx.z;
    int t0 = blockIdx.x * 32;
    int c0 = blockIdx.y * 32;
    const float* src = se + (size_t)b * CDIM * TDIM;
    #pragma unroll
    for (int j = 0; j < 32; j += 8) {
        int c = c0 + threadIdx.y + j;
        int t = t0 + threadIdx.x;
        if (t < TDIM) tile[threadIdx.y + j][threadIdx.x] = src[(size_t)c * TDIM + t];
    }
    __syncthreads();
    #pragma unroll
    for (int j = 0; j < 32; j += 8) {
        int t = t0 + threadIdx.y + j;
        int c = c0 + threadIdx.x;
        if (t < TDIM) g_E[(size_t)(b * TDIM + t) * CDIM + c] = tile[threadIdx.x][threadIdx.y + j];
    }
}

// ---------------- split fp32 -> bf16 hi + lo ----------------
__global__ void k_splitE() {
    int i = blockIdx.x * 256 + threadIdx.x;
    if (i >= NROWS * CDIM / 4) return;
    float4 a = ((const float4*)g_E)[i];
    __nv_bfloat16 h0 = __float2bfloat16(a.x), h1 = __float2bfloat16(a.y);
    __nv_bfloat16 h2 = __float2bfloat16(a.z), h3 = __float2bfloat16(a.w);
    __nv_bfloat16 l0 = __float2bfloat16(a.x - __bfloat162float(h0));
    __nv_bfloat16 l1 = __float2bfloat16(a.y - __bfloat162float(h1));
    __nv_bfloat16 l2 = __float2bfloat16(a.z - __bfloat162float(h2));
    __nv_bfloat16 l3 = __float2bfloat16(a.w - __bfloat162float(h3));
    __nv_bfloat162* ph = (__nv_bfloat162*)g_Ehi;
    __nv_bfloat162* pl = (__nv_bfloat162*)g_Elo;
    __nv_bfloat162 t;
    t.x = h0; t.y = h1; ph[2 * i] = t;
    t.x = h2; t.y = h3; ph[2 * i + 1] = t;
    t.x = l0; t.y = l1; pl[2 * i] = t;
    t.x = l2; t.y = l3; pl[2 * i + 1] = t;
}

__global__ void k_splitCB(const float* __restrict__ cb) {
    int i = blockIdx.x * 256 + threadIdx.x;
    if (i >= VCNT * CDIM / 4) return;
    float4 a = ((const float4*)cb)[i];
    __nv_bfloat16 h0 = __float2bfloat16(a.x), h1 = __float2bfloat16(a.y);
    __nv_bfloat16 h2 = __float2bfloat16(a.z), h3 = __float2bfloat16(a.w);
    __nv_bfloat16 l0 = __float2bfloat16(a.x - __bfloat162float(h0));
    __nv_bfloat16 l1 = __float2bfloat16(a.y - __bfloat162float(h1));
    __nv_bfloat16 l2 = __float2bfloat16(a.z - __bfloat162float(h2));
    __nv_bfloat16 l3 = __float2bfloat16(a.w - __bfloat162float(h3));
    __nv_bfloat162* ph = (__nv_bfloat162*)g_Bhi;
    __nv_bfloat162* pl = (__nv_bfloat162*)g_Blo;
    __nv_bfloat162 t;
    t.x = h0; t.y = h1; ph[2 * i] = t;
    t.x = h2; t.y = h3; ph[2 * i + 1] = t;
    t.x = l0; t.y = l1; pl[2 * i] = t;
    t.x = l2; t.y = l3; pl[2 * i + 1] = t;
}

// ---------------- row squared-norms ----------------
__global__ void k_esq() {
    int row  = blockIdx.x * 8 + (threadIdx.x >> 5);
    int lane = threadIdx.x & 31;
    if (row >= NROWS) return;
    const float4* p = (const float4*)(g_E + (size_t)row * CDIM);
    float s = 0.f;
    #pragma unroll
    for (int i = lane; i < CDIM / 4; i += 32) {
        float4 q = p[i];
        s += q.x * q.x + q.y * q.y + q.z * q.z + q.w * q.w;
    }
    s = warpSumF(s);
    if (lane == 0) g_esq[row] = s;
}

__global__ void k_csq(const float* __restrict__ cb) {
    int row  = blockIdx.x * 8 + (threadIdx.x >> 5);
    int lane = threadIdx.x & 31;
    if (row >= VCNT) return;
    const float4* p = (const float4*)(cb + (size_t)row * CDIM);
    float s = 0.f;
    #pragma unroll
    for (int i = lane; i < CDIM / 4; i += 32) {
        float4 q = p[i];
        s += q.x * q.x + q.y * q.y + q.z * q.z + q.w * q.w;
    }
    s = warpSumF(s);
    if (lane == 0) g_csq[row] = s;
}

// ---------------- mma.sync GEMM ----------------
// D2[m][n] = esq[m] + csq[n] - 2 * dot(E[m], CB[n]); dot = hi*hi + hi*lo + lo*hi in bf16 MMAs.
__device__ __forceinline__ void load_stage(uint32_t sbase, int m0, int n0, int k0, int tid) {
    #pragma unroll
    for (int it = 0; it < 2; it++) {
        int g = tid + it * 256;          // 0..511: 128 rows x 4 granules of 16B
        int row = g >> 2, gc = g & 3;
        uint32_t off = (uint32_t)(row * ROWB + gc * 16);
        size_t ia = (size_t)(m0 + row) * CDIM + k0 + gc * 8;
        size_t ib = (size_t)(n0 + row) * CDIM + k0 + gc * 8;
        cp16(sbase + off, g_Ehi + ia);
        cp16(sbase + OPBYTES + off, g_Elo + ia);
        cp16(sbase + 2 * OPBYTES + off, g_Bhi + ib);
        cp16(sbase + 3 * OPBYTES + off, g_Blo + ib);
    }
}

__global__ void __launch_bounds__(256, 1) k_gemm_mma() {
    extern __shared__ char smem[];
    uint32_t sb = smem_u32(smem);
    const int tid = threadIdx.x, wid = tid >> 5, lane = tid & 31;
    const int m0 = blockIdx.y * BM, n0 = blockIdx.x * BN;
    const int wm = (wid >> 2) * 64;       // warp m-offset (0 or 64)
    const int wn = (wid & 3) * 32;        // warp n-offset (0,32,64,96)

    float acc[4][4][4] = {};

    // ldmatrix lane row/col assignment (x4: lanes 0-7 m0, 8-15 m1, 16-23 m2, 24-31 m3)
    const int lA_row = wm + (lane & 7) + ((lane >> 3) & 1) * 8;
    const int lA_k   = (lane >> 4) * 8;
    const int lB_row = wn + (lane & 7) + (lane >> 4) * 8;
    const int lB_k   = ((lane >> 3) & 1) * 8;

    load_stage(sb + 0 * STG, m0, n0, 0 * BK, tid);
    asm volatile("cp.async.commit_group;" ::: "memory");
    load_stage(sb + 1 * STG, m0, n0, 1 * BK, tid);
    asm volatile("cp.async.commit_group;" ::: "memory");
    load_stage(sb + 2 * STG, m0, n0, 2 * BK, tid);
    asm volatile("cp.async.commit_group;" ::: "memory");

    for (int s = 0; s < NKIT; s++) {
        asm volatile("cp.async.wait_group 2;" ::: "memory");
        __syncthreads();
        const uint32_t cur = sb + (uint32_t)(s & 3) * STG;
        #pragma unroll
        for (int kk = 0; kk < 2; kk++) {
            uint32_t aH[4][4], aL[4][4], bH[4][2], bL[4][2];
            #pragma unroll
            for (int fm = 0; fm < 4; fm++) {
                uint32_t ad = cur + (uint32_t)((lA_row + fm * 16) * ROWB + (kk * 16 + lA_k) * 2);
                LDSM4(aH[fm], ad);
                LDSM4(aL[fm], ad + OPBYTES);
            }
            #pragma unroll
            for (int h = 0; h < 2; h++) {
                uint32_t bd = cur + 2 * OPBYTES +
                              (uint32_t)((lB_row + h * 16) * ROWB + (kk * 16 + lB_k) * 2);
                uint32_t t0[4], t1[4];
                LDSM4(t0, bd);
                bH[2 * h][0] = t0[0]; bH[2 * h][1] = t0[1];
                bH[2 * h + 1][0] = t0[2]; bH[2 * h + 1][1] = t0[3];
                LDSM4(t1, bd + OPBYTES);
                bL[2 * h][0] = t1[0]; bL[2 * h][1] = t1[1];
                bL[2 * h + 1][0] = t1[2]; bL[2 * h + 1][1] = t1[3];
            }
            #pragma unroll
            for (int fm = 0; fm < 4; fm++)
                #pragma unroll
                for (int fn = 0; fn < 4; fn++) {
                    mma16816(acc[fm][fn], aH[fm], bH[fn]);
                    mma16816(acc[fm][fn], aH[fm], bL[fn]);
                    mma16816(acc[fm][fn], aL[fm], bH[fn]);
                }
        }
        if (s + 3 < NKIT) load_stage(sb + (uint32_t)((s + 3) & 3) * STG, m0, n0, (s + 3) * BK, tid);
        asm volatile("cp.async.commit_group;" ::: "memory");
    }

    // epilogue: c frag regs {0,1} = row g, cols 2l..2l+1; {2,3} = row g+8
    const int g = lane >> 2, l2 = (lane & 3) * 2;
    #pragma unroll
    for (int fm = 0; fm < 4; fm++) {
        #pragma unroll
        for (int half = 0; half < 2; half++) {
            int r = m0 + wm + fm * 16 + g + half * 8;
            if (r < NROWS) {
                float es = g_esq[r];
                float* orow = g_D2 + (size_t)r * VCNT;
                #pragma unroll
                for (int fn = 0; fn < 4; fn++) {
                    int c = n0 + wn + fn * 8 + l2;
                    float2 o;
                    o.x = es + g_csq[c]     - 2.f * acc[fm][fn][half * 2 + 0];
                    o.y = es + g_csq[c + 1] - 2.f * acc[fm][fn][half * 2 + 1];
                    *(float2*)(orow + c) = o;
                }
            }
        }
    }
}

// ---------------- per-row top-K select + loss ----------------
__global__ void __launch_bounds__(256) k_select(int dummy) {
    const int n   = blockIdx.x;
    const int tid = threadIdx.x;
    const float* row = g_D2 + (size_t)n * VCNT;

    float    v[16];
    unsigned key[16];
    unsigned long long lmin = ~0ull;
    #pragma unroll
    for (int i = 0; i < 16; i++) {
        int idx = tid + i * 256;
        float x = fmaxf(row[idx], 0.f);
        v[i] = x;
        key[i] = __float_as_uint(x);
        unsigned long long p = ((unsigned long long)key[i] << 32) | (unsigned)idx;
        lmin = (p < lmin) ? p : lmin;
    }

    __shared__ unsigned long long s_min;
    __shared__ unsigned hist[256];
    __shared__ unsigned s_prefix, s_krem;
    __shared__ float s_wf[8];
    __shared__ int   s_wc[8], s_we[8];

    if (tid == 0) { s_min = ~0ull; s_prefix = 0u; s_krem = KSEL; }
    __syncthreads();
    atomicMin(&s_min, lmin);

    for (int pass = 0; pass < 4; pass++) {
        int shift = 24 - 8 * pass;
        hist[tid] = 0;
        __syncthreads();
        unsigned pref = s_prefix;
        #pragma unroll
        for (int i = 0; i < 16; i++) {
            bool part = (pass == 0) || (((key[i] ^ pref) >> (shift + 8)) == 0u);
            if (part) atomicAdd(&hist[(key[i] >> shift) & 255u], 1u);
        }
        __syncthreads();
        if (tid == 0) {
            unsigned k = s_krem, cum = 0, b = 0;
            for (; b < 256u; b++) {
                unsigned c = hist[b];
                if (cum + c >= k) break;
                cum += c;
            }
            s_prefix |= b << shift;
            s_krem = k - cum;
        }
        __syncthreads();
    }

    const unsigned Tkey = s_prefix;
    const unsigned cb   = KSEL - s_krem;
    const unsigned long long mn = s_min;
    const float dmin = sqrtf(__uint_as_float((unsigned)(mn >> 32)));
    const int   amin = (int)(mn & 0xffffffffu);

    const int   code = g_codes[n];
    const float d2c  = fmaxf(__ldg(&row[code]), 0.f);
    const unsigned kc = __float_as_uint(d2c);

    float sw = 0.f;
    int cl = 0, ce = 0;
    #pragma unroll
    for (int i = 0; i < 16; i++) {
        unsigned kk = key[i];
        if (kk < Tkey) sw += expf(dmin - sqrtf(v[i]));
        cl += (kk < kc);
        ce += (kk == kc) && ((tid + i * 256) < code);
    }
    sw = warpSumF(sw); cl = warpSumI(cl); ce = warpSumI(ce);
    int w = tid >> 5, lane = tid & 31;
    if (lane == 0) { s_wf[w] = sw; s_wc[w] = cl; s_we[w] = ce; }
    __syncthreads();

    if (tid == 0) {
        float swt = 0.f; int clt = 0, cet = 0;
        #pragma unroll
        for (int i = 0; i < 8; i++) { swt += s_wf[i]; clt += s_wc[i]; cet += s_we[i]; }

        float Td = sqrtf(__uint_as_float(Tkey));
        float wT = expf(dmin - Td);
        float dc = sqrtf(d2c);
        bool in_topk = (clt + cet) < KSEL;
        float S;
        if (in_topk) S = swt + (float)(KSEL - cb) * wT;
        else         S = swt + (float)(KSEL - 1 - cb) * wT + expf(dmin - dc);
        g_row_loss[n]  = dc - dmin + logf(S);
        g_row_match[n] = (amin == code) ? 1.f : 0.f;
    }
}

// ---------------- final deterministic reduction ----------------
__global__ void k_finalize(float* __restrict__ out) {
    __shared__ double sl[256], sm[256];
    int tid = threadIdx.x;
    double l = 0.0, m = 0.0;
    for (int i = tid; i < NROWS; i += 256) {
        l += (double)g_row_loss[i];
        m += (double)g_row_match[i];
    }
    sl[tid] = l; sm[tid] = m;
    __syncthreads();
    for (int s = 128; s > 0; s >>= 1) {
        if (tid < s) { sl[tid] += sl[tid + s]; sm[tid] += sm[tid + s]; }
        __syncthreads();
    }
    if (tid == 0) {
        out[0] = (float)(sl[0] / NROWS);
        out[1] = (float)(sm[0] / NROWS);
        out[2] = (float)(sm[0] / NROWS);
        out[3] = 1.0f;
    }
}

// ---------------- launch ----------------
extern "C" void kernel_launch(void* const* d_in, const int* in_sizes, int n_in,
                              void* d_out, int out_size) {
    const float* se    = (const float*)d_in[0];
    const int*   codes = (const int*)d_in[1];
    const float* cb    = (const float*)d_in[2];
    float* out = (float*)d_out;
    (void)in_sizes; (void)n_in; (void)out_size;

    static int attr_done = 0;
    if (!attr_done) {
        cudaFuncSetAttribute(k_gemm_mma, cudaFuncAttributeMaxDynamicSharedMemorySize, SMEM_GEMM);
        attr_done = 1;
    }

    k_detect<<<1, 256>>>(codes);
    k_normcodes<<<(NROWS + 255) / 256, 256>>>(codes);
    k_transpose<<<dim3((TDIM + 31) / 32, CDIM / 32, BDIMB), dim3(32, 8)>>>(se);
    k_splitE<<<(NROWS * CDIM / 4 + 255) / 256, 256>>>();
    k_splitCB<<<(VCNT * CDIM / 4 + 255) / 256, 256>>>(cb);
    k_esq<<<(NROWS + 7) / 8, 256>>>();
    k_csq<<<VCNT / 8, 256>>>(cb);
    k_gemm_mma<<<dim3(VCNT / BN, MPAD / BM), 256, SMEM_GEMM>>>();
    k_select<<<NROWS, 256>>>(0);
    k_finalize<<<1, 256>>>(out);
}

// round 4
// speedup vs baseline: 4.1322x; 1.9024x over previous
#include <cuda_runtime.h>
#include <cuda_fp16.h>
#include <cstdint>

#define NROWS 12000     // B*T = 8*1500
#define MPAD  12032     // 94 * 128
#define BDIMB 8
#define TDIM  1500
#define CDIM  512
#define VCNT  4096
#define KSEL  100
#define DELTA 0.25f     // exact-rescue window on approx d^2 (~25 sigma of fp16 GEMM error)
#define LCAP  32

// ---- mma.sync GEMM tiling (fp16 single-term) ----
#define BM 128
#define BN 128
#define BK 32
#define ROWB 80                       // smem leading dim bytes (40 halfs), ldmatrix conflict-free
#define OPBYTES (128 * ROWB)          // 10240 per operand per stage
#define STG (2 * OPBYTES)             // 20480 (A, B)
#define NSTAGE 4
#define SMEM_GEMM (NSTAGE * STG)      // 81920 -> 2 CTAs/SM
#define NKIT (CDIM / BK)              // 16

// ---------------- scratch (device globals: no allocations allowed) ----------------
__device__ __align__(16) float g_E[(size_t)NROWS * CDIM];      // fp32 tokens x C (exact path)
__device__ __align__(16) __half g_Eh[(size_t)MPAD * CDIM];     // rows >= NROWS stay 0
__device__ __align__(16) __half g_Bh[(size_t)VCNT * CDIM];
__device__ float g_esq[NROWS];
__device__ float g_csq[VCNT];
__device__ __align__(16) float g_D2[(size_t)NROWS * VCNT];     // 196.6 MB approx d^2
__device__ int   g_codes[NROWS];
__device__ int   g_is64;
__device__ float g_row_loss[NROWS];
__device__ float g_row_match[NROWS];

// ---------------- helpers ----------------
__device__ __forceinline__ float warpSumF(float v) {
    #pragma unroll
    for (int o = 16; o > 0; o >>= 1) v += __shfl_down_sync(0xffffffffu, v, o);
    return v;
}
__device__ __forceinline__ int warpSumI(int v) {
    #pragma unroll
    for (int o = 16; o > 0; o >>= 1) v += __shfl_down_sync(0xffffffffu, v, o);
    return v;
}
__device__ __forceinline__ uint32_t smem_u32(const void* p) {
    uint32_t a;
    asm("{ .reg .u64 t; cvta.to.shared.u64 t, %1; cvt.u32.u64 %0, t; }" : "=r"(a) : "l"(p));
    return a;
}
__device__ __forceinline__ void cp16(uint32_t dst, const void* src) {
    asm volatile("cp.async.cg.shared.global [%0], [%1], 16;" :: "r"(dst), "l"(src));
}
#define LDSM4(r, a) \
    asm volatile("ldmatrix.sync.aligned.m8n8.x4.shared.b16 {%0,%1,%2,%3}, [%4];" \
        : "=r"((r)[0]), "=r"((r)[1]), "=r"((r)[2]), "=r"((r)[3]) : "r"(a))

__device__ __forceinline__ void mma16816(float* c, const uint32_t* a, const uint32_t* b) {
    asm volatile(
        "mma.sync.aligned.m16n8k16.row.col.f32.f16.f16.f32 "
        "{%0,%1,%2,%3}, {%4,%5,%6,%7}, {%8,%9}, {%0,%1,%2,%3};"
        : "+f"(c[0]), "+f"(c[1]), "+f"(c[2]), "+f"(c[3])
        : "r"(a[0]), "r"(a[1]), "r"(a[2]), "r"(a[3]), "r"(b[0]), "r"(b[1]));
}

// ---------------- int64-vs-int32 teacher_codes detection ----------------
__global__ void k_detect(const int* __restrict__ w) {
    __shared__ int any_nonzero;
    if (threadIdx.x == 0) any_nonzero = 0;
    __syncthreads();
    int bad = 0;
    for (int i = threadIdx.x; i < 6000; i += 256)
        if (w[2 * i + 1] != 0) bad = 1;
    if (bad) any_nonzero = 1;
    __syncthreads();
    if (threadIdx.x == 0) g_is64 = (any_nonzero == 0) ? 1 : 0;
}

__global__ void k_normcodes(const int* __restrict__ w) {
    int i = blockIdx.x * 256 + threadIdx.x;
    if (i >= NROWS) return;
    g_codes[i] = g_is64 ? w[2 * i] : w[i];
}

// ---------------- transpose student_emb (B,C,T) -> g_E fp32 + g_Eh fp16 ----------------
__global__ void k_transpose(const float* __restrict__ se) {
    __shared__ float tile[32][33];
    int b  = blockIdx.z;
    int t0 = blockIdx.x * 32;
    int c0 = blockIdx.y * 32;
    const float* src = se + (size_t)b * CDIM * TDIM;
    #pragma unroll
    for (int j = 0; j < 32; j += 8) {
        int c = c0 + threadIdx.y + j;
        int t = t0 + threadIdx.x;
        if (t < TDIM) tile[threadIdx.y + j][threadIdx.x] = src[(size_t)c * TDIM + t];
    }
    __syncthreads();
    #pragma unroll
    for (int j = 0; j < 32; j += 8) {
        int t = t0 + threadIdx.y + j;
        int c = c0 + threadIdx.x;
        if (t < TDIM) {
            float x = tile[threadIdx.x][threadIdx.y + j];
            size_t o = (size_t)(b * TDIM + t) * CDIM + c;
            g_E[o]  = x;
            g_Eh[o] = __float2half_rn(x);
        }
    }
}

// ---------------- codebook: fp16 copy + squared norms (fused) ----------------
__global__ void k_prepCB(const float* __restrict__ cb) {
    int row  = blockIdx.x * 8 + (threadIdx.x >> 5);
    int lane = threadIdx.x & 31;
    if (row >= VCNT) return;
    const float4* p = (const float4*)(cb + (size_t)row * CDIM);
    __half2* o = (__half2*)(g_Bh + (size_t)row * CDIM);
    float s = 0.f;
    #pragma unroll
    for (int i = lane; i < CDIM / 4; i += 32) {
        float4 q = p[i];
        s += q.x * q.x + q.y * q.y + q.z * q.z + q.w * q.w;
        o[2 * i]     = __floats2half2_rn(q.x, q.y);
        o[2 * i + 1] = __floats2half2_rn(q.z, q.w);
    }
    s = warpSumF(s);
    if (lane == 0) g_csq[row] = s;
}

// ---------------- row squared-norms of E ----------------
__global__ void k_esq() {
    int row  = blockIdx.x * 8 + (threadIdx.x >> 5);
    int lane = threadIdx.x & 31;
    if (row >= NROWS) return;
    const float4* p = (const float4*)(g_E + (size_t)row * CDIM);
    float s = 0.f;
    #pragma unroll
    for (int i = lane; i < CDIM / 4; i += 32) {
        float4 q = p[i];
        s += q.x * q.x + q.y * q.y + q.z * q.z + q.w * q.w;
    }
    s = warpSumF(s);
    if (lane == 0) g_esq[row] = s;
}

// ---------------- fp16 mma.sync GEMM: approx D2 ----------------
__device__ __forceinline__ void load_stage(uint32_t sbase, int m0, int n0, int k0, int tid) {
    #pragma unroll
    for (int it = 0; it < 2; it++) {
        int g = tid + it * 256;          // 0..511: 128 rows x 4 granules of 16B
        int row = g >> 2, gc = g & 3;
        uint32_t off = (uint32_t)(row * ROWB + gc * 16);
        cp16(sbase + off,           g_Eh + (size_t)(m0 + row) * CDIM + k0 + gc * 8);
        cp16(sbase + OPBYTES + off, g_Bh + (size_t)(n0 + row) * CDIM + k0 + gc * 8);
    }
}

__global__ void __launch_bounds__(256, 2) k_gemm_mma() {
    extern __shared__ char smem[];
    uint32_t sb = smem_u32(smem);
    const int tid = threadIdx.x, wid = tid >> 5, lane = tid & 31;
    const int m0 = blockIdx.y * BM, n0 = blockIdx.x * BN;
    const int wm = (wid >> 2) * 64;
    const int wn = (wid & 3) * 32;

    float acc[4][4][4] = {};

    const int lA_row = wm + (lane & 7) + ((lane >> 3) & 1) * 8;
    const int lA_k   = (lane >> 4) * 8;
    const int lB_row = wn + (lane & 7) + (lane >> 4) * 8;
    const int lB_k   = ((lane >> 3) & 1) * 8;

    load_stage(sb + 0 * STG, m0, n0, 0 * BK, tid);
    asm volatile("cp.async.commit_group;" ::: "memory");
    load_stage(sb + 1 * STG, m0, n0, 1 * BK, tid);
    asm volatile("cp.async.commit_group;" ::: "memory");
    load_stage(sb + 2 * STG, m0, n0, 2 * BK, tid);
    asm volatile("cp.async.commit_group;" ::: "memory");

    for (int s = 0; s < NKIT; s++) {
        asm volatile("cp.async.wait_group 2;" ::: "memory");
        __syncthreads();
        const uint32_t cur = sb + (uint32_t)(s & 3) * STG;
        #pragma unroll
        for (int kk = 0; kk < 2; kk++) {
            uint32_t aH[4][4], bH[4][2];
            #pragma unroll
            for (int fm = 0; fm < 4; fm++) {
                uint32_t ad = cur + (uint32_t)((lA_row + fm * 16) * ROWB + (kk * 16 + lA_k) * 2);
                LDSM4(aH[fm], ad);
            }
            #pragma unroll
            for (int h = 0; h < 2; h++) {
                uint32_t bd = cur + OPBYTES +
                              (uint32_t)((lB_row + h * 16) * ROWB + (kk * 16 + lB_k) * 2);
                uint32_t t0[4];
                LDSM4(t0, bd);
                bH[2 * h][0] = t0[0]; bH[2 * h][1] = t0[1];
                bH[2 * h + 1][0] = t0[2]; bH[2 * h + 1][1] = t0[3];
            }
            #pragma unroll
            for (int fm = 0; fm < 4; fm++)
                #pragma unroll
                for (int fn = 0; fn < 4; fn++)
                    mma16816(acc[fm][fn], aH[fm], bH[fn]);
        }
        if (s + 3 < NKIT) load_stage(sb + (uint32_t)((s + 3) & 3) * STG, m0, n0, (s + 3) * BK, tid);
        asm volatile("cp.async.commit_group;" ::: "memory");
    }

    const int g = lane >> 2, l2 = (lane & 3) * 2;
    #pragma unroll
    for (int fm = 0; fm < 4; fm++) {
        #pragma unroll
        for (int half = 0; half < 2; half++) {
            int r = m0 + wm + fm * 16 + g + half * 8;
            if (r < NROWS) {
                float es = g_esq[r];
                float* orow = g_D2 + (size_t)r * VCNT;
                #pragma unroll
                for (int fn = 0; fn < 4; fn++) {
                    int c = n0 + wn + fn * 8 + l2;
                    float2 o;
                    o.x = es + g_csq[c]     - 2.f * acc[fm][fn][half * 2 + 0];
                    o.y = es + g_csq[c + 1] - 2.f * acc[fm][fn][half * 2 + 1];
                    *(float2*)(orow + c) = o;
                }
            }
        }
    }
}

// ---------------- per-row top-K select + exact rescue + loss ----------------
__global__ void __launch_bounds__(256) k_select(const float* __restrict__ cb) {
    const int n   = blockIdx.x;
    const int tid = threadIdx.x;
    const int wid = tid >> 5, lane = tid & 31;
    const float* row = g_D2 + (size_t)n * VCNT;
    const int code = g_codes[n];

    float    v[16];
    unsigned key[16];
    unsigned lmin = ~0u;
    #pragma unroll
    for (int i = 0; i < 16; i++) {
        int idx = tid + i * 256;
        float x = fmaxf(row[idx], 0.f);
        v[i] = x;
        key[i] = __float_as_uint(x);
        lmin = min(lmin, key[i]);
    }

    __shared__ unsigned s_minkey;
    __shared__ unsigned hist[256];
    __shared__ unsigned s_prefix, s_krem;
    __shared__ int   s_lidx[LCAP];
    __shared__ float s_lval[LCAP];
    __shared__ int   s_lcnt;
    __shared__ float s_dmin, s_dc;
    __shared__ int   s_amin;
    __shared__ float s_wf[8];
    __shared__ int   s_wc[8], s_we[8];

    if (tid == 0) {
        s_minkey = ~0u; s_prefix = 0u; s_krem = KSEL;
        s_lcnt = 1; s_lidx[0] = code;         // code always rescued
    }
    __syncthreads();
    atomicMin(&s_minkey, lmin);

    // ---- 4-pass radix select: exact rank-KSEL key of approx d^2 ----
    for (int pass = 0; pass < 4; pass++) {
        int shift = 24 - 8 * pass;
        hist[tid] = 0;
        __syncthreads();
        unsigned pref = s_prefix;
        #pragma unroll
        for (int i = 0; i < 16; i++) {
            bool part = (pass == 0) || (((key[i] ^ pref) >> (shift + 8)) == 0u);
            if (part) atomicAdd(&hist[(key[i] >> shift) & 255u], 1u);
        }
        __syncthreads();
        if (tid < 32) {
            unsigned k = s_krem;
            unsigned loc[8], s0 = 0;
            #pragma unroll
            for (int j = 0; j < 8; j++) { loc[j] = hist[tid * 8 + j]; s0 += loc[j]; }
            unsigned pre = s0;
            #pragma unroll
            for (int o = 1; o < 32; o <<= 1) {
                unsigned t = __shfl_up_sync(0xffffffffu, pre, o);
                if (lane >= o) pre += t;
            }
            unsigned excl = pre - s0;
            if (excl < k && k <= excl + s0) {
                unsigned cum = excl;
                #pragma unroll
                for (int j = 0; j < 8; j++) {
                    if (cum + loc[j] >= k) { s_prefix |= (unsigned)(tid * 8 + j) << shift;
                                             s_krem = k - cum; break; }
                    cum += loc[j];
                }
            }
        }
        __syncthreads();
    }

    const unsigned Tkey = s_prefix;
    const unsigned cbel = KSEL - s_krem;      // strictly-below-threshold count

    // ---- window collect: approx d^2 within DELTA of approx min ----
    const unsigned kwin = __float_as_uint(__uint_as_float(s_minkey) + DELTA);
    #pragma unroll
    for (int i = 0; i < 16; i++) {
        if (key[i] < kwin) {
            int pos = atomicAdd(&s_lcnt, 1);
            if (pos < LCAP) s_lidx[pos] = tid + i * 256;
        }
    }
    __syncthreads();
    const int cnt = min(s_lcnt, LCAP);

    // ---- exact fp32 recompute of rescued candidates (warp per entry) ----
    const float* Er = g_E + (size_t)n * CDIM;
    for (int e = wid; e < cnt; e += 8) {
        int vi = s_lidx[e];
        const float4* A = (const float4*)Er;
        const float4* B = (const float4*)(cb + (size_t)vi * CDIM);
        float d = 0.f;
        #pragma unroll 4
        for (int i = lane; i < CDIM / 4; i += 32) {
            float4 a = A[i], b = B[i];
            d += a.x * b.x + a.y * b.y + a.z * b.z + a.w * b.w;
        }
        d = warpSumF(d);
        if (lane == 0) s_lval[e] = fmaxf(g_esq[n] + g_csq[vi] - 2.f * d, 0.f);
    }
    __syncthreads();

    if (tid == 0) {
        float best = 3.4e38f, dco = 0.f;
        int bidx = 0x7fffffff;
        for (int e = 0; e < cnt; e++) {
            float val = s_lval[e]; int ix = s_lidx[e];
            if (val < best || (val == best && ix < bidx)) { best = val; bidx = ix; }
            if (ix == code) dco = val;
        }
        s_dmin = sqrtf(best);
        s_amin = bidx;
        s_dc   = sqrtf(dco);
    }
    __syncthreads();

    const float dmin = s_dmin;
    const float d2c_apx = fmaxf(__ldg(&row[code]), 0.f);
    const unsigned kc = __float_as_uint(d2c_apx);

    // partial sums over approx keys
    float sw = 0.f;
    int cl = 0, ce = 0;
    #pragma unroll
    for (int i = 0; i < 16; i++) {
        unsigned kk = key[i];
        if (kk < Tkey) sw += expf(dmin - sqrtf(v[i]));
        cl += (kk < kc);
        ce += (kk == kc) && ((tid + i * 256) < code);
    }
    sw = warpSumF(sw); cl = warpSumI(cl); ce = warpSumI(ce);
    if (lane == 0) { s_wf[wid] = sw; s_wc[wid] = cl; s_we[wid] = ce; }
    __syncthreads();

    if (tid == 0) {
        float swt = 0.f; int clt = 0, cet = 0;
        #pragma unroll
        for (int i = 0; i < 8; i++) { swt += s_wf[i]; clt += s_wc[i]; cet += s_we[i]; }

        float Td = sqrtf(__uint_as_float(Tkey));
        float wT = expf(dmin - Td);
        float dc = s_dc;
        bool in_topk = (clt + cet) < KSEL;     // top_k tie-break: smaller index wins
        float S;
        if (in_topk) S = swt + (float)(KSEL - cbel) * wT;
        else         S = swt + (float)(KSEL - 1 - cbel) * wT + expf(dmin - dc);
        g_row_loss[n]  = dc - dmin + logf(S);
        g_row_match[n] = (s_amin == code) ? 1.f : 0.f;
    }
}

// ---------------- final deterministic reduction ----------------
__global__ void k_finalize(float* __restrict__ out) {
    __shared__ double sl[256], sm[256];
    int tid = threadIdx.x;
    double l = 0.0, m = 0.0;
    for (int i = tid; i < NROWS; i += 256) {
        l += (double)g_row_loss[i];
        m += (double)g_row_match[i];
    }
    sl[tid] = l; sm[tid] = m;
    __syncthreads();
    for (int s = 128; s > 0; s >>= 1) {
        if (tid < s) { sl[tid] += sl[tid + s]; sm[tid] += sm[tid + s]; }
        __syncthreads();
    }
    if (tid == 0) {
        out[0] = (float)(sl[0] / NROWS);
        out[1] = (float)(sm[0] / NROWS);
        out[2] = (float)(sm[0] / NROWS);
        out[3] = 1.0f;
    }
}

// ---------------- launch ----------------
extern "C" void kernel_launch(void* const* d_in, const int* in_sizes, int n_in,
                              void* d_out, int out_size) {
    const float* se    = (const float*)d_in[0];
    const int*   codes = (const int*)d_in[1];
    const float* cb    = (const float*)d_in[2];
    float* out = (float*)d_out;
    (void)in_sizes; (void)n_in; (void)out_size;

    static int attr_done = 0;
    if (!attr_done) {
        cudaFuncSetAttribute(k_gemm_mma, cudaFuncAttributeMaxDynamicSharedMemorySize, SMEM_GEMM);
        attr_done = 1;
    }

    k_detect<<<1, 256>>>(codes);                                            // 1
    k_normcodes<<<(NROWS + 255) / 256, 256>>>(codes);                       // 2
    k_transpose<<<dim3((TDIM + 31) / 32, CDIM / 32, BDIMB), dim3(32, 8)>>>(se); // 3
    k_prepCB<<<VCNT / 8, 256>>>(cb);                                        // 4
    k_esq<<<(NROWS + 7) / 8, 256>>>();                                      // 5
    k_gemm_mma<<<dim3(VCNT / BN, MPAD / BM), 256, SMEM_GEMM>>>();           // 6 (ncu -s 5 lands here)
    k_select<<<NROWS, 256>>>(cb);                                           // 7
    k_finalize<<<1, 256>>>(out);                                            // 8
}

// round 7
// speedup vs baseline: 4.2941x; 1.0392x over previous
#include <cuda_runtime.h>
#include <cuda_fp16.h>
#include <cstdint>

#define NROWS 12000     // B*T = 8*1500
#define MPAD  12032     // 94 * 128
#define BDIMB 8
#define TDIM  1500
#define CDIM  512
#define VCNT  4096
#define KSEL  100
#define DELTA 0.25f     // exact-rescue window on approx d^2 (~25 sigma of fp16 GEMM error)
#define LCAP  32

// ---- mma.sync GEMM tiling (fp16 single-term) ----
#define BM 128
#define BN 128
#define BK 32
#define ROWB 80                       // smem leading dim bytes (40 halfs), ldmatrix conflict-free
#define OPBYTES (128 * ROWB)          // 10240 per operand per stage
#define STG (2 * OPBYTES)             // 20480 (A, B)
#define NSTAGE 4
#define SMEM_GEMM (NSTAGE * STG)      // 81920 -> 2 CTAs/SM
#define NKIT (CDIM / BK)              // 16

// ---------------- scratch (device globals: no allocations allowed) ----------------
__device__ __align__(16) float g_E[(size_t)NROWS * CDIM];      // fp32 tokens x C (exact path)
__device__ __align__(16) __half g_Eh[(size_t)MPAD * CDIM];     // rows >= NROWS stay 0
__device__ __align__(16) __half g_Bh[(size_t)VCNT * CDIM];
__device__ float g_esq[NROWS];
__device__ float g_csq[VCNT];
__device__ __align__(16) float g_D2[(size_t)NROWS * VCNT];     // 196.6 MB approx d^2
__device__ int   g_codes[NROWS];
__device__ int   g_is64;
__device__ float g_row_loss[NROWS];
__device__ float g_row_match[NROWS];

// ---------------- helpers ----------------
__device__ __forceinline__ float warpSumF(float v) {
    #pragma unroll
    for (int o = 16; o > 0; o >>= 1) v += __shfl_down_sync(0xffffffffu, v, o);
    return v;
}
__device__ __forceinline__ int warpSumI(int v) {
    #pragma unroll
    for (int o = 16; o > 0; o >>= 1) v += __shfl_down_sync(0xffffffffu, v, o);
    return v;
}
__device__ __forceinline__ uint32_t smem_u32(const void* p) {
    uint32_t a;
    asm("{ .reg .u64 t; cvta.to.shared.u64 t, %1; cvt.u32.u64 %0, t; }" : "=r"(a) : "l"(p));
    return a;
}
__device__ __forceinline__ void cp16(uint32_t dst, const void* src) {
    asm volatile("cp.async.cg.shared.global [%0], [%1], 16;" :: "r"(dst), "l"(src));
}
#define LDSM4(r, a) \
    asm volatile("ldmatrix.sync.aligned.m8n8.x4.shared.b16 {%0,%1,%2,%3}, [%4];" \
        : "=r"((r)[0]), "=r"((r)[1]), "=r"((r)[2]), "=r"((r)[3]) : "r"(a))

__device__ __forceinline__ void mma16816(float* c, const uint32_t* a, const uint32_t* b) {
    asm volatile(
        "mma.sync.aligned.m16n8k16.row.col.f32.f16.f16.f32 "
        "{%0,%1,%2,%3}, {%4,%5,%6,%7}, {%8,%9}, {%0,%1,%2,%3};"
        : "+f"(c[0]), "+f"(c[1]), "+f"(c[2]), "+f"(c[3])
        : "r"(a[0]), "r"(a[1]), "r"(a[2]), "r"(a[3]), "r"(b[0]), "r"(b[1]));
}

// ---------------- transpose student_emb (B,C,T) -> g_E fp32 + g_Eh fp16 ----------------
__global__ void k_transpose(const float* __restrict__ se) {
    __shared__ float tile[32][33];
    int b  = blockIdx.z;
    int t0 = blockIdx.x * 32;
    int c0 = blockIdx.y * 32;
    const float* src = se + (size_t)b * CDIM * TDIM;
    #pragma unroll
    for (int j = 0; j < 32; j += 8) {
        int c = c0 + threadIdx.y + j;
        int t = t0 + threadIdx.x;
        if (t < TDIM) tile[threadIdx.y + j][threadIdx.x] = src[(size_t)c * TDIM + t];
    }
    __syncthreads();
    #pragma unroll
    for (int j = 0; j < 32; j += 8) {
        int t = t0 + threadIdx.y + j;
        int c = c0 + threadIdx.x;
        if (t < TDIM) {
            float x = tile[threadIdx.x][threadIdx.y + j];
            size_t o = (size_t)(b * TDIM + t) * CDIM + c;
            g_E[o]  = x;
            g_Eh[o] = __float2half_rn(x);
        }
    }
}

// ---------------- codebook: fp16 copy + squared norms (fused) ----------------
__global__ void k_prepCB(const float* __restrict__ cb) {
    int row  = blockIdx.x * 8 + (threadIdx.x >> 5);
    int lane = threadIdx.x & 31;
    if (row >= VCNT) return;
    const float4* p = (const float4*)(cb + (size_t)row * CDIM);
    __half2* o = (__half2*)(g_Bh + (size_t)row * CDIM);
    float s = 0.f;
    #pragma unroll
    for (int i = lane; i < CDIM / 4; i += 32) {
        float4 q = p[i];
        s += q.x * q.x + q.y * q.y + q.z * q.z + q.w * q.w;
        o[2 * i]     = __floats2half2_rn(q.x, q.y);
        o[2 * i + 1] = __floats2half2_rn(q.z, q.w);
    }
    s = warpSumF(s);
    if (lane == 0) g_csq[row] = s;
}

// ---------------- row squared-norms of E ----------------
__global__ void k_esq() {
    int row  = blockIdx.x * 8 + (threadIdx.x >> 5);
    int lane = threadIdx.x & 31;
    if (row >= NROWS) return;
    const float4* p = (const float4*)(g_E + (size_t)row * CDIM);
    float s = 0.f;
    #pragma unroll
    for (int i = lane; i < CDIM / 4; i += 32) {
        float4 q = p[i];
        s += q.x * q.x + q.y * q.y + q.z * q.z + q.w * q.w;
    }
    s = warpSumF(s);
    if (lane == 0) g_esq[row] = s;
}

// ---------------- fp16 mma.sync GEMM: approx D2 ----------------
__device__ __forceinline__ void load_stage(uint32_t sbase, int m0, int n0, int k0, int tid) {
    #pragma unroll
    for (int it = 0; it < 2; it++) {
        int g = tid + it * 256;          // 0..511: 128 rows x 4 granules of 16B
        int row = g >> 2, gc = g & 3;
        uint32_t off = (uint32_t)(row * ROWB + gc * 16);
        cp16(sbase + off,           g_Eh + (size_t)(m0 + row) * CDIM + k0 + gc * 8);
        cp16(sbase + OPBYTES + off, g_Bh + (size_t)(n0 + row) * CDIM + k0 + gc * 8);
    }
}

__global__ void __launch_bounds__(256, 2) k_gemm_mma() {
    extern __shared__ char smem[];
    uint32_t sb = smem_u32(smem);
    const int tid = threadIdx.x, wid = tid >> 5, lane = tid & 31;
    const int m0 = blockIdx.y * BM, n0 = blockIdx.x * BN;
    const int wm = (wid >> 2) * 64;
    const int wn = (wid & 3) * 32;

    float acc[4][4][4] = {};

    const int lA_row = wm + (lane & 7) + ((lane >> 3) & 1) * 8;
    const int lA_k   = (lane >> 4) * 8;
    const int lB_row = wn + (lane & 7) + (lane >> 4) * 8;
    const int lB_k   = ((lane >> 3) & 1) * 8;

    load_stage(sb + 0 * STG, m0, n0, 0 * BK, tid);
    asm volatile("cp.async.commit_group;" ::: "memory");
    load_stage(sb + 1 * STG, m0, n0, 1 * BK, tid);
    asm volatile("cp.async.commit_group;" ::: "memory");
    load_stage(sb + 2 * STG, m0, n0, 2 * BK, tid);
    asm volatile("cp.async.commit_group;" ::: "memory");

    #pragma unroll
    for (int s = 0; s < NKIT; s++) {
        asm volatile("cp.async.wait_group 2;" ::: "memory");
        __syncthreads();
        // issue next-stage loads FIRST: slot (s+3)&3 == (s-1)&3 was consumed by all
        // warps before this barrier, so it is free; LDGSTS issue overlaps the MMAs.
        if (s + 3 < NKIT) load_stage(sb + (uint32_t)((s + 3) & 3) * STG, m0, n0, (s + 3) * BK, tid);
        asm volatile("cp.async.commit_group;" ::: "memory");

        const uint32_t cur = sb + (uint32_t)(s & 3) * STG;
        #pragma unroll
        for (int kk = 0; kk < 2; kk++) {
            uint32_t aH[4][4], bH[4][2];
            #pragma unroll
            for (int fm = 0; fm < 4; fm++) {
                uint32_t ad = cur + (uint32_t)((lA_row + fm * 16) * ROWB + (kk * 16 + lA_k) * 2);
                LDSM4(aH[fm], ad);
            }
            #pragma unroll
            for (int h = 0; h < 2; h++) {
                uint32_t bd = cur + OPBYTES +
                              (uint32_t)((lB_row + h * 16) * ROWB + (kk * 16 + lB_k) * 2);
                uint32_t t0[4];
                LDSM4(t0, bd);
                bH[2 * h][0] = t0[0]; bH[2 * h][1] = t0[1];
                bH[2 * h + 1][0] = t0[2]; bH[2 * h + 1][1] = t0[3];
            }
            #pragma unroll
            for (int fm = 0; fm < 4; fm++)
                #pragma unroll
                for (int fn = 0; fn < 4; fn++)
                    mma16816(acc[fm][fn], aH[fm], bH[fn]);
        }
    }

    const int g = lane >> 2, l2 = (lane & 3) * 2;
    #pragma unroll
    for (int fm = 0; fm < 4; fm++) {
        #pragma unroll
        for (int half = 0; half < 2; half++) {
            int r = m0 + wm + fm * 16 + g + half * 8;
            if (r < NROWS) {
                float es = g_esq[r];
                float* orow = g_D2 + (size_t)r * VCNT;
                #pragma unroll
                for (int fn = 0; fn < 4; fn++) {
                    int c = n0 + wn + fn * 8 + l2;
                    float2 o;
                    o.x = es + g_csq[c]     - 2.f * acc[fm][fn][half * 2 + 0];
                    o.y = es + g_csq[c + 1] - 2.f * acc[fm][fn][half * 2 + 1];
                    *(float2*)(orow + c) = o;
                }
            }
        }
    }
}

// ---------------- int64-vs-int32 teacher_codes detection (GLOBAL, bounded) ----------------
// Reads ONLY the first 12000 int32 words: in-bounds whether the buffer holds
// 12000 int32 (12000 words) or 12000 int64 (24000 words). If int64, words at odd
// indices (hi-words of codes 0..5999) are all zero; if int32, they are 6000
// random codes in [0,4096) -- essentially never all zero.
__global__ void k_detect(const int* __restrict__ w) {
    __shared__ int any_nonzero;
    if (threadIdx.x == 0) any_nonzero = 0;
    __syncthreads();
    int bad = 0;
    for (int i = threadIdx.x; i < 6000; i += 256)
        if (w[2 * i + 1] != 0) bad = 1;
    if (bad) any_nonzero = 1;   // benign race
    __syncthreads();
    if (threadIdx.x == 0) g_is64 = (any_nonzero == 0) ? 1 : 0;
}

__global__ void k_normcodes(const int* __restrict__ w) {
    int i = blockIdx.x * 256 + threadIdx.x;
    if (i >= NROWS) return;
    g_codes[i] = g_is64 ? w[2 * i] : w[i];   // little-endian lo word
}

// ---------------- per-row top-K select + exact rescue + loss ----------------
__global__ void __launch_bounds__(256) k_select(const float* __restrict__ cb) {
    const int n   = blockIdx.x;
    const int tid = threadIdx.x;
    const int wid = tid >> 5, lane = tid & 31;
    const float* row = g_D2 + (size_t)n * VCNT;
    const int code = g_codes[n];
    const float d2c_apx = fmaxf(__ldg(&row[code]), 0.f);

    float    v[16];
    unsigned key[16];
    unsigned lmin = ~0u;
    #pragma unroll
    for (int i = 0; i < 16; i++) {
        int idx = tid + i * 256;
        float x = fmaxf(row[idx], 0.f);
        v[i] = x;
        key[i] = __float_as_uint(x);
        lmin = min(lmin, key[i]);
    }

    __shared__ unsigned s_minkey;
    __shared__ unsigned hist[256];
    __shared__ unsigned s_prefix, s_krem;
    __shared__ int   s_lidx[LCAP];
    __shared__ float s_lval[LCAP];
    __shared__ int   s_lcnt;
    __shared__ float s_dmin, s_dc;
    __shared__ int   s_amin;
    __shared__ float s_wf[8];
    __shared__ int   s_wc[8], s_we[8];

    if (tid == 0) {
        s_minkey = ~0u; s_prefix = 0u; s_krem = KSEL;
        s_lcnt = 1; s_lidx[0] = code;         // code always rescued
    }
    __syncthreads();
    atomicMin(&s_minkey, lmin);

    // ---- 4-pass radix select: exact rank-KSEL key of approx d^2 ----
    for (int pass = 0; pass < 4; pass++) {
        int shift = 24 - 8 * pass;
        hist[tid] = 0;
        __syncthreads();
        unsigned pref = s_prefix;
        #pragma unroll
        for (int i = 0; i < 16; i++) {
            bool part = (pass == 0) || (((key[i] ^ pref) >> (shift + 8)) == 0u);
            if (part) atomicAdd(&hist[(key[i] >> shift) & 255u], 1u);
        }
        __syncthreads();
        if (tid < 32) {
            unsigned k = s_krem;
            unsigned loc[8], s0 = 0;
            #pragma unroll
            for (int j = 0; j < 8; j++) { loc[j] = hist[tid * 8 + j]; s0 += loc[j]; }
            unsigned pre = s0;
            #pragma unroll
            for (int o = 1; o < 32; o <<= 1) {
                unsigned t = __shfl_up_sync(0xffffffffu, pre, o);
                if (lane >= o) pre += t;
            }
            unsigned excl = pre - s0;
            if (excl < k && k <= excl + s0) {
                unsigned cum = excl;
                #pragma unroll
                for (int j = 0; j < 8; j++) {
                    if (cum + loc[j] >= k) { s_prefix |= (unsigned)(tid * 8 + j) << shift;
                                             s_krem = k - cum; break; }
                    cum += loc[j];
                }
            }
        }
        __syncthreads();
    }

    const unsigned Tkey = s_prefix;
    const unsigned cbel = KSEL - s_krem;      // strictly-below-threshold count

    // ---- window collect: approx d^2 within DELTA of approx min ----
    const unsigned kwin = __float_as_uint(__uint_as_float(s_minkey) + DELTA);
    #pragma unroll
    for (int i = 0; i < 16; i++) {
        if (key[i] < kwin) {
            int pos = atomicAdd(&s_lcnt, 1);
            if (pos < LCAP) s_lidx[pos] = tid + i * 256;
        }
    }
    __syncthreads();
    const int cnt = min(s_lcnt, LCAP);

    // ---- exact fp32 recompute of rescued candidates (warp per entry) ----
    const float* Er = g_E + (size_t)n * CDIM;
    for (int e = wid; e < cnt; e += 8) {
        int vi = s_lidx[e];
        const float4* A = (const float4*)Er;
        const float4* B = (const float4*)(cb + (size_t)vi * CDIM);
        float d = 0.f;
        #pragma unroll 4
        for (int i = lane; i < CDIM / 4; i += 32) {
            float4 a = A[i], b = B[i];
            d += a.x * b.x + a.y * b.y + a.z * b.z + a.w * b.w;
        }
        d = warpSumF(d);
        if (lane == 0) s_lval[e] = fmaxf(g_esq[n] + g_csq[vi] - 2.f * d, 0.f);
    }
    __syncthreads();

    if (tid == 0) {
        float best = 3.4e38f, dco = 0.f;
        int bidx = 0x7fffffff;
        for (int e = 0; e < cnt; e++) {
            float val = s_lval[e]; int ix = s_lidx[e];
            if (val < best || (val == best && ix < bidx)) { best = val; bidx = ix; }
            if (ix == code) dco = val;
        }
        s_dmin = sqrtf(best);
        s_amin = bidx;
        s_dc   = sqrtf(dco);
    }
    __syncthreads();

    const float dmin = s_dmin;
    const unsigned kc = __float_as_uint(d2c_apx);

    // partial sums over approx keys
    float sw = 0.f;
    int cl = 0, ce = 0;
    #pragma unroll
    for (int i = 0; i < 16; i++) {
        unsigned kk = key[i];
        if (kk < Tkey) sw += __expf(dmin - sqrtf(v[i]));
        cl += (kk < kc);
        ce += (kk == kc) && ((tid + i * 256) < code);
    }
    sw = warpSumF(sw); cl = warpSumI(cl); ce = warpSumI(ce);
    if (lane == 0) { s_wf[wid] = sw; s_wc[wid] = cl; s_we[wid] = ce; }
    __syncthreads();

    if (tid == 0) {
        float swt = 0.f; int clt = 0, cet = 0;
        #pragma unroll
        for (int i = 0; i < 8; i++) { swt += s_wf[i]; clt += s_wc[i]; cet += s_we[i]; }

        float Td = sqrtf(__uint_as_float(Tkey));
        float wT = __expf(dmin - Td);
        float dc = s_dc;
        bool in_topk = (clt + cet) < KSEL;     // top_k tie-break: smaller index wins
        float S;
        if (in_topk) S = swt + (float)(KSEL - cbel) * wT;
        else         S = swt + (float)(KSEL - 1 - cbel) * wT + __expf(dmin - dc);
        g_row_loss[n]  = dc - dmin + logf(S);
        g_row_match[n] = (s_amin == code) ? 1.f : 0.f;
    }
}

// ---------------- final deterministic reduction ----------------
__global__ void k_finalize(float* __restrict__ out) {
    __shared__ double sl[256], sm[256];
    int tid = threadIdx.x;
    double l = 0.0, m = 0.0;
    for (int i = tid; i < NROWS; i += 256) {
        l += (double)g_row_loss[i];
        m += (double)g_row_match[i];
    }
    sl[tid] = l; sm[tid] = m;
    __syncthreads();
    for (int s = 128; s > 0; s >>= 1) {
        if (tid < s) { sl[tid] += sl[tid + s]; sm[tid] += sm[tid + s]; }
        __syncthreads();
    }
    if (tid == 0) {
        out[0] = (float)(sl[0] / NROWS);
        out[1] = (float)(sm[0] / NROWS);
        out[2] = (float)(sm[0] / NROWS);
        out[3] = 1.0f;
    }
}

// ---------------- launch ----------------
extern "C" void kernel_launch(void* const* d_in, const int* in_sizes, int n_in,
                              void* d_out, int out_size) {
    const float* se    = (const float*)d_in[0];
    const int*   codes = (const int*)d_in[1];
    const float* cb    = (const float*)d_in[2];
    float* out = (float*)d_out;
    (void)in_sizes; (void)n_in; (void)out_size;

    static int attr_done = 0;
    if (!attr_done) {
        cudaFuncSetAttribute(k_gemm_mma, cudaFuncAttributeMaxDynamicSharedMemorySize, SMEM_GEMM);
        attr_done = 1;
    }

    k_transpose<<<dim3((TDIM + 31) / 32, CDIM / 32, BDIMB), dim3(32, 8)>>>(se); // 1
    k_prepCB<<<VCNT / 8, 256>>>(cb);                                        // 2
    k_esq<<<(NROWS + 7) / 8, 256>>>();                                      // 3
    k_gemm_mma<<<dim3(VCNT / BN, MPAD / BM), 256, SMEM_GEMM>>>();           // 4 <- ncu samples here
    k_detect<<<1, 256>>>(codes);                                            // 5
    k_normcodes<<<(NROWS + 255) / 256, 256>>>(codes);                       // 6
    k_select<<<NROWS, 256>>>(cb);                                           // 7
    k_finalize<<<1, 256>>>(out);                                            // 8
}